// round 2
// baseline (speedup 1.0000x reference)
#include <cuda_runtime.h>
#include <math.h>

#define N_SEL   8192
#define N_FEAT  256
#define K_SUB   256
#define N_PERS  4
#define E_FULL  262144
#define E_RAW   262144
#define N_TOT   8192
#define VLEN    (N_PERS * N_FEAT)   /* 1024 */
#define EPSILON 0.5f
#define LAMB1   0.5f

// Static device scratch (allocation-free rule)
__device__ float        g_v[(size_t)N_SEL * VLEN];                 // 32 MB normalized weighted features
__device__ unsigned int g_mask[((size_t)N_SEL * N_SEL) / 32];      // 8 MB dedup bitmask
__device__ float        g_score[K_SUB];

// ---------------- score normalization (1 block, 256 threads) ----------------
__global__ void score_kernel(const int* __restrict__ belong,
                             const float* __restrict__ score) {
    __shared__ float ssum[K_SUB];
    int t = threadIdx.x;
    ssum[t] = 0.0f;
    __syncthreads();
    atomicAdd(&ssum[belong[t]], score[t]);
    __syncthreads();
    g_score[t] = score[t] / ssum[belong[t]];
}

// ---------------- build v = 0.5 * normalize(x (.) w_p), per (node, persp) ----
// grid: N_SEL blocks of 128 threads; warp p handles perspective p
__global__ void prep_kernel(const float* __restrict__ x,
                            const float* __restrict__ w) {
    int node = blockIdx.x;
    int p    = threadIdx.x >> 5;
    int lane = threadIdx.x & 31;
    const float* xr = x + (size_t)node * N_FEAT;
    const float* wr = w + (size_t)p * N_FEAT;

    float vals[8];
    float ss = 0.0f;
#pragma unroll
    for (int k = 0; k < 8; k++) {
        int d = lane + k * 32;
        float h = xr[d] * wr[d];
        vals[k] = h;
        ss += h * h;
    }
#pragma unroll
    for (int o = 16; o > 0; o >>= 1) ss += __shfl_xor_sync(0xffffffffu, ss, o);

    float scale = 0.5f / (sqrtf(ss) + 1e-12f);
    float* vr = g_v + (size_t)node * VLEN + (size_t)p * N_FEAT;
#pragma unroll
    for (int k = 0; k < 8; k++) vr[lane + k * 32] = vals[k] * scale;
}

// ---------------- zeroing ----------------
__global__ void zero_out_kernel(float4* __restrict__ out, size_t n4) {
    size_t i = (size_t)blockIdx.x * blockDim.x + threadIdx.x;
    size_t stride = (size_t)gridDim.x * blockDim.x;
    float4 z = make_float4(0.f, 0.f, 0.f, 0.f);
    for (; i < n4; i += stride) out[i] = z;
}

__global__ void zero_mask_kernel() {
    size_t n4 = ((size_t)N_SEL * N_SEL / 32) / 4;  // uint4 count
    uint4* p = reinterpret_cast<uint4*>(g_mask);
    size_t i = (size_t)blockIdx.x * blockDim.x + threadIdx.x;
    size_t stride = (size_t)gridDim.x * blockDim.x;
    uint4 z = make_uint4(0u, 0u, 0u, 0u);
    for (; i < n4; i += stride) p[i] = z;
}

// ---------------- per-edge dot + threshold + scatter ----------------
// one warp per edge; 8 warps / block
__global__ void edge_kernel(const int* __restrict__ fe,
                            const int* __restrict__ batch,
                            const int* __restrict__ mapping,
                            float* __restrict__ out) {
    int e = blockIdx.x * 8 + (threadIdx.x >> 5);
    int lane = threadIdx.x & 31;
    if (e >= E_FULL) return;

    int i = fe[e];
    int j = fe[E_FULL + e];
    if (i == j) return;  // diagonal removed

    const float4* vi = reinterpret_cast<const float4*>(g_v + (size_t)i * VLEN);
    const float4* vj = reinterpret_cast<const float4*>(g_v + (size_t)j * VLEN);

    float acc = 0.0f;
#pragma unroll
    for (int k = 0; k < 8; k++) {
        float4 a = vi[lane + k * 32];
        float4 b = vj[lane + k * 32];
        acc += a.x * b.x + a.y * b.y + a.z * b.z + a.w * b.w;
    }
#pragma unroll
    for (int o = 16; o > 0; o >>= 1) acc += __shfl_xor_sync(0xffffffffu, acc, o);

    if (acc > EPSILON && lane == 0) {
        // dedup: duplicate (i,j) edges contribute exactly once (mask .set semantics)
        size_t cell = (size_t)i * N_SEL + (size_t)j;
        unsigned bit = 1u << (cell & 31);
        unsigned old = atomicOr(&g_mask[cell >> 5], bit);
        if (!(old & bit)) {
            float wgt = g_score[batch[i]] * LAMB1;
            atomicAdd(&out[(size_t)mapping[i] * N_TOT + mapping[j]], acc * wgt);
        }
    }
}

// ---------------- raw graph edges ----------------
__global__ void raw_kernel(const int* __restrict__ re, float* __restrict__ out) {
    int e = blockIdx.x * blockDim.x + threadIdx.x;
    if (e >= E_RAW) return;
    int r0 = re[e];
    int r1 = re[E_RAW + e];
    atomicAdd(&out[(size_t)r0 * N_TOT + r1], 1.0f - LAMB1);
}

extern "C" void kernel_launch(void* const* d_in, const int* in_sizes, int n_in,
                              void* d_out, int out_size) {
    const float* x        = (const float*)d_in[0];
    const float* mw       = (const float*)d_in[1];
    const int*   batch    = (const int*)d_in[2];
    const int*   mapping  = (const int*)d_in[3];
    const int*   belong   = (const int*)d_in[4];
    const float* score    = (const float*)d_in[5];
    const int*   fe       = (const int*)d_in[6];
    const int*   re       = (const int*)d_in[7];
    float* out = (float*)d_out;

    // zero output (64M floats) and dedup mask
    size_t n4 = ((size_t)N_TOT * N_TOT) / 4;
    zero_out_kernel<<<2048, 256>>>(reinterpret_cast<float4*>(out), n4);
    zero_mask_kernel<<<256, 256>>>();

    // normalized subgraph scores
    score_kernel<<<1, K_SUB>>>(belong, score);

    // normalized weighted feature table
    prep_kernel<<<N_SEL, 128>>>(x, mw);

    // learned edges
    edge_kernel<<<E_FULL / 8, 256>>>(fe, batch, mapping, out);

    // raw edges
    raw_kernel<<<E_RAW / 256, 256>>>(re, out);
}

// round 3
// speedup vs baseline: 1.4109x; 1.4109x over previous
#include <cuda_runtime.h>
#include <cuda_bf16.h>
#include <math.h>

#define N_SEL   8192
#define N_FEAT  256
#define K_SUB   256
#define N_PERS  4
#define E_FULL  262144
#define E_RAW   262144
#define N_TOT   8192
#define VLEN    (N_PERS * N_FEAT)   /* 1024 */
#define EPSILON 0.5f
#define LAMB1   0.5f

// Static device scratch (allocation-free rule)
__device__ __nv_bfloat16 g_v[(size_t)N_SEL * VLEN];               // 16 MB normalized weighted features (bf16)
__device__ unsigned int  g_mask[((size_t)N_SEL * N_SEL) / 32];    // 8 MB dedup bitmask
__device__ float         g_score[K_SUB];

// ---------------- score normalization (1 block, 256 threads) ----------------
__global__ void score_kernel(const int* __restrict__ belong,
                             const float* __restrict__ score) {
    __shared__ float ssum[K_SUB];
    int t = threadIdx.x;
    ssum[t] = 0.0f;
    __syncthreads();
    atomicAdd(&ssum[belong[t]], score[t]);
    __syncthreads();
    g_score[t] = score[t] / ssum[belong[t]];
}

// ---------------- build v = 0.5 * normalize(x (.) w_p) -> bf16 table --------
// grid: N_SEL blocks of 128 threads; warp p handles perspective p.
// Each lane owns 8 CONTIGUOUS elements -> one uint4 store of 8 packed bf16.
__global__ void prep_kernel(const float* __restrict__ x,
                            const float* __restrict__ w) {
    int node = blockIdx.x;
    int p    = threadIdx.x >> 5;
    int lane = threadIdx.x & 31;
    const float4* xr = reinterpret_cast<const float4*>(x + (size_t)node * N_FEAT);
    const float4* wr = reinterpret_cast<const float4*>(w + (size_t)p * N_FEAT);

    float4 a0 = xr[lane * 2 + 0], a1 = xr[lane * 2 + 1];
    float4 b0 = wr[lane * 2 + 0], b1 = wr[lane * 2 + 1];
    float h[8];
    h[0] = a0.x * b0.x; h[1] = a0.y * b0.y; h[2] = a0.z * b0.z; h[3] = a0.w * b0.w;
    h[4] = a1.x * b1.x; h[5] = a1.y * b1.y; h[6] = a1.z * b1.z; h[7] = a1.w * b1.w;

    float ss = 0.0f;
#pragma unroll
    for (int k = 0; k < 8; k++) ss += h[k] * h[k];
#pragma unroll
    for (int o = 16; o > 0; o >>= 1) ss += __shfl_xor_sync(0xffffffffu, ss, o);

    float scale = 0.5f / (sqrtf(ss) + 1e-12f);

    __nv_bfloat162 pk[4];
#pragma unroll
    for (int k = 0; k < 4; k++)
        pk[k] = __floats2bfloat162_rn(h[2 * k] * scale, h[2 * k + 1] * scale);

    uint4* vr = reinterpret_cast<uint4*>(g_v + (size_t)node * VLEN + (size_t)p * N_FEAT);
    vr[lane] = *reinterpret_cast<uint4*>(pk);
}

// ---------------- zeroing ----------------
__global__ void zero_out_kernel(float4* __restrict__ out, size_t n4) {
    size_t i = (size_t)blockIdx.x * blockDim.x + threadIdx.x;
    size_t stride = (size_t)gridDim.x * blockDim.x;
    float4 z = make_float4(0.f, 0.f, 0.f, 0.f);
    for (; i < n4; i += stride) out[i] = z;
}

__global__ void zero_mask_kernel() {
    size_t n4 = ((size_t)N_SEL * N_SEL / 32) / 4;  // uint4 count
    uint4* p = reinterpret_cast<uint4*>(g_mask);
    size_t i = (size_t)blockIdx.x * blockDim.x + threadIdx.x;
    size_t stride = (size_t)gridDim.x * blockDim.x;
    uint4 z = make_uint4(0u, 0u, 0u, 0u);
    for (; i < n4; i += stride) p[i] = z;
}

// ---------------- per-edge dot + threshold + scatter ----------------
// one warp per edge; 8 warps / block; rows are 1024 bf16 = 2 KB = 128 uint4
__global__ void edge_kernel(const int* __restrict__ fe,
                            const int* __restrict__ batch,
                            const int* __restrict__ mapping,
                            float* __restrict__ out) {
    int e = blockIdx.x * 8 + (threadIdx.x >> 5);
    int lane = threadIdx.x & 31;
    if (e >= E_FULL) return;

    int i = fe[e];
    int j = fe[E_FULL + e];
    if (i == j) return;  // diagonal removed

    const uint4* vi = reinterpret_cast<const uint4*>(g_v + (size_t)i * VLEN);
    const uint4* vj = reinterpret_cast<const uint4*>(g_v + (size_t)j * VLEN);

    float acc = 0.0f;
#pragma unroll
    for (int k = 0; k < 4; k++) {
        uint4 ua = vi[lane + k * 32];
        uint4 ub = vj[lane + k * 32];
        const __nv_bfloat162* pa = reinterpret_cast<const __nv_bfloat162*>(&ua);
        const __nv_bfloat162* pb = reinterpret_cast<const __nv_bfloat162*>(&ub);
#pragma unroll
        for (int q = 0; q < 4; q++) {
            float2 fa = __bfloat1622float2(pa[q]);
            float2 fb = __bfloat1622float2(pb[q]);
            acc = fmaf(fa.x, fb.x, acc);
            acc = fmaf(fa.y, fb.y, acc);
        }
    }
#pragma unroll
    for (int o = 16; o > 0; o >>= 1) acc += __shfl_xor_sync(0xffffffffu, acc, o);

    if (acc > EPSILON && lane == 0) {
        // dedup: duplicate (i,j) edges contribute exactly once (mask .set semantics)
        size_t cell = (size_t)i * N_SEL + (size_t)j;
        unsigned bit = 1u << (cell & 31);
        unsigned old = atomicOr(&g_mask[cell >> 5], bit);
        if (!(old & bit)) {
            float wgt = g_score[batch[i]] * LAMB1;
            atomicAdd(&out[(size_t)mapping[i] * N_TOT + mapping[j]], acc * wgt);
        }
    }
}

// ---------------- raw graph edges ----------------
__global__ void raw_kernel(const int* __restrict__ re, float* __restrict__ out) {
    int e = blockIdx.x * blockDim.x + threadIdx.x;
    if (e >= E_RAW) return;
    int r0 = re[e];
    int r1 = re[E_RAW + e];
    atomicAdd(&out[(size_t)r0 * N_TOT + r1], 1.0f - LAMB1);
}

extern "C" void kernel_launch(void* const* d_in, const int* in_sizes, int n_in,
                              void* d_out, int out_size) {
    const float* x        = (const float*)d_in[0];
    const float* mw       = (const float*)d_in[1];
    const int*   batch    = (const int*)d_in[2];
    const int*   mapping  = (const int*)d_in[3];
    const int*   belong   = (const int*)d_in[4];
    const float* score    = (const float*)d_in[5];
    const int*   fe       = (const int*)d_in[6];
    const int*   re       = (const int*)d_in[7];
    float* out = (float*)d_out;

    // zero output (64M floats) and dedup mask
    size_t n4 = ((size_t)N_TOT * N_TOT) / 4;
    zero_out_kernel<<<2048, 256>>>(reinterpret_cast<float4*>(out), n4);
    zero_mask_kernel<<<256, 256>>>();

    // normalized subgraph scores
    score_kernel<<<1, K_SUB>>>(belong, score);

    // normalized weighted feature table (bf16)
    prep_kernel<<<N_SEL, 128>>>(x, mw);

    // learned edges
    edge_kernel<<<E_FULL / 8, 256>>>(fe, batch, mapping, out);

    // raw edges
    raw_kernel<<<E_RAW / 256, 256>>>(re, out);
}

// round 5
// speedup vs baseline: 1.4838x; 1.0517x over previous
#include <cuda_runtime.h>
#include <cuda_bf16.h>
#include <cuda_fp8.h>
#include <math.h>

#define N_SEL   8192
#define N_FEAT  256
#define K_SUB   256
#define N_PERS  4
#define E_FULL  262144
#define E_RAW   262144
#define N_TOT   8192
#define VLEN    (N_PERS * N_FEAT)   /* 1024 */
#define EPSILON 0.5f
#define LAMB1   0.5f

// ---------------- static device scratch (allocation-free rule) --------------
__device__ unsigned char g_v8[(size_t)N_SEL * VLEN];              // 8 MB fp8(e4m3) feature table
__device__ unsigned int  g_mask[((size_t)N_SEL * N_SEL) / 32];    // 8 MB dedup bitmask
__device__ float         g_score[K_SUB];

// ---------------- score normalization (1 block, 256 threads) ----------------
__global__ void score_kernel(const int* __restrict__ belong,
                             const float* __restrict__ score) {
    __shared__ float ssum[K_SUB];
    int t = threadIdx.x;
    ssum[t] = 0.0f;
    __syncthreads();
    atomicAdd(&ssum[belong[t]], score[t]);
    __syncthreads();
    g_score[t] = score[t] / ssum[belong[t]];
}

// ---------------- build v = 0.5 * normalize(x (.) w_p) -> fp8 table ---------
// grid: N_SEL blocks of 128 threads; warp p handles perspective p.
// Each lane owns 8 contiguous elements -> one 8-byte store of packed e4m3.
__global__ void prep_kernel(const float* __restrict__ x,
                            const float* __restrict__ w) {
    int node = blockIdx.x;
    int p    = threadIdx.x >> 5;
    int lane = threadIdx.x & 31;
    const float4* xr = reinterpret_cast<const float4*>(x + (size_t)node * N_FEAT);
    const float4* wr = reinterpret_cast<const float4*>(w + (size_t)p * N_FEAT);

    float4 a0 = xr[lane * 2 + 0], a1 = xr[lane * 2 + 1];
    float4 b0 = wr[lane * 2 + 0], b1 = wr[lane * 2 + 1];
    float h[8];
    h[0] = a0.x * b0.x; h[1] = a0.y * b0.y; h[2] = a0.z * b0.z; h[3] = a0.w * b0.w;
    h[4] = a1.x * b1.x; h[5] = a1.y * b1.y; h[6] = a1.z * b1.z; h[7] = a1.w * b1.w;

    float ss = 0.0f;
#pragma unroll
    for (int k = 0; k < 8; k++) ss += h[k] * h[k];
#pragma unroll
    for (int o = 16; o > 0; o >>= 1) ss += __shfl_xor_sync(0xffffffffu, ss, o);

    float scale = 0.5f / (sqrtf(ss) + 1e-12f);

    unsigned int w0, w1;
    {
        __nv_fp8x2_storage_t p0 = __nv_cvt_float2_to_fp8x2(
            make_float2(h[0] * scale, h[1] * scale), __NV_SATFINITE, __NV_E4M3);
        __nv_fp8x2_storage_t p1 = __nv_cvt_float2_to_fp8x2(
            make_float2(h[2] * scale, h[3] * scale), __NV_SATFINITE, __NV_E4M3);
        __nv_fp8x2_storage_t p2 = __nv_cvt_float2_to_fp8x2(
            make_float2(h[4] * scale, h[5] * scale), __NV_SATFINITE, __NV_E4M3);
        __nv_fp8x2_storage_t p3 = __nv_cvt_float2_to_fp8x2(
            make_float2(h[6] * scale, h[7] * scale), __NV_SATFINITE, __NV_E4M3);
        w0 = (unsigned int)p0 | ((unsigned int)p1 << 16);
        w1 = (unsigned int)p2 | ((unsigned int)p3 << 16);
    }
    uint2* vr = reinterpret_cast<uint2*>(g_v8 + (size_t)node * VLEN + (size_t)p * N_FEAT);
    vr[lane] = make_uint2(w0, w1);
}

// ---------------- zeroing ----------------
__global__ void zero_out_kernel(float4* __restrict__ out, size_t n4) {
    size_t i = (size_t)blockIdx.x * blockDim.x + threadIdx.x;
    size_t stride = (size_t)gridDim.x * blockDim.x;
    float4 z = make_float4(0.f, 0.f, 0.f, 0.f);
    for (; i < n4; i += stride) out[i] = z;
}

__global__ void zero_mask_kernel() {
    size_t n4 = ((size_t)N_SEL * N_SEL / 32) / 4;  // uint4 count
    uint4* p = reinterpret_cast<uint4*>(g_mask);
    size_t i = (size_t)blockIdx.x * blockDim.x + threadIdx.x;
    size_t stride = (size_t)gridDim.x * blockDim.x;
    uint4 z = make_uint4(0u, 0u, 0u, 0u);
    for (; i < n4; i += stride) p[i] = z;
}

// ---------------- per-edge dot + threshold + scatter ----------------
// one warp per edge; 8 warps / block; row = 1024 e4m3 bytes = 64 uint4
__global__ void edge_kernel(const int* __restrict__ fe,
                            const int* __restrict__ batch,
                            const int* __restrict__ mapping,
                            float* __restrict__ out) {
    int e = blockIdx.x * 8 + (threadIdx.x >> 5);
    int lane = threadIdx.x & 31;
    if (e >= E_FULL) return;

    int i = fe[e];
    int j = fe[E_FULL + e];
    if (i == j) return;  // diagonal removed

    const uint4* vi = reinterpret_cast<const uint4*>(g_v8 + (size_t)i * VLEN);
    const uint4* vj = reinterpret_cast<const uint4*>(g_v8 + (size_t)j * VLEN);

    float acc = 0.0f;
#pragma unroll
    for (int k = 0; k < 2; k++) {
        uint4 ua = vi[lane + k * 32];
        uint4 ub = vj[lane + k * 32];
        const unsigned int* wa = reinterpret_cast<const unsigned int*>(&ua);
        const unsigned int* wb = reinterpret_cast<const unsigned int*>(&ub);
#pragma unroll
        for (int q = 0; q < 4; q++) {
            __half2_raw alo = __nv_cvt_fp8x2_to_halfraw2(
                (__nv_fp8x2_storage_t)(wa[q] & 0xffffu), __NV_E4M3);
            __half2_raw ahi = __nv_cvt_fp8x2_to_halfraw2(
                (__nv_fp8x2_storage_t)(wa[q] >> 16), __NV_E4M3);
            __half2_raw blo = __nv_cvt_fp8x2_to_halfraw2(
                (__nv_fp8x2_storage_t)(wb[q] & 0xffffu), __NV_E4M3);
            __half2_raw bhi = __nv_cvt_fp8x2_to_halfraw2(
                (__nv_fp8x2_storage_t)(wb[q] >> 16), __NV_E4M3);
            float2 fa0 = __half22float2(*reinterpret_cast<__half2*>(&alo));
            float2 fa1 = __half22float2(*reinterpret_cast<__half2*>(&ahi));
            float2 fb0 = __half22float2(*reinterpret_cast<__half2*>(&blo));
            float2 fb1 = __half22float2(*reinterpret_cast<__half2*>(&bhi));
            acc = fmaf(fa0.x, fb0.x, acc);
            acc = fmaf(fa0.y, fb0.y, acc);
            acc = fmaf(fa1.x, fb1.x, acc);
            acc = fmaf(fa1.y, fb1.y, acc);
        }
    }
#pragma unroll
    for (int o = 16; o > 0; o >>= 1) acc += __shfl_xor_sync(0xffffffffu, acc, o);

    if (acc > EPSILON && lane == 0) {
        // dedup: duplicate (i,j) edges contribute exactly once (mask .set semantics);
        // duplicates carry identical values, so first-writer-wins is deterministic
        size_t cell = (size_t)i * N_SEL + (size_t)j;
        unsigned bit = 1u << (cell & 31);
        unsigned old = atomicOr(&g_mask[cell >> 5], bit);
        if (!(old & bit)) {
            float wgt = g_score[batch[i]] * LAMB1;
            atomicAdd(&out[(size_t)mapping[i] * N_TOT + mapping[j]], acc * wgt);
        }
    }
}

// ---------------- raw graph edges ----------------
__global__ void raw_kernel(const int* __restrict__ re, float* __restrict__ out) {
    int e = blockIdx.x * blockDim.x + threadIdx.x;
    if (e >= E_RAW) return;
    int r0 = re[e];
    int r1 = re[E_RAW + e];
    atomicAdd(&out[(size_t)r0 * N_TOT + r1], 1.0f - LAMB1);
}

extern "C" void kernel_launch(void* const* d_in, const int* in_sizes, int n_in,
                              void* d_out, int out_size) {
    const float* x        = (const float*)d_in[0];
    const float* mw       = (const float*)d_in[1];
    const int*   batch    = (const int*)d_in[2];
    const int*   mapping  = (const int*)d_in[3];
    const int*   belong   = (const int*)d_in[4];
    const float* score    = (const float*)d_in[5];
    const int*   fe       = (const int*)d_in[6];
    const int*   re       = (const int*)d_in[7];
    float* out = (float*)d_out;

    // zero output (64M floats) and dedup mask
    size_t n4 = ((size_t)N_TOT * N_TOT) / 4;
    zero_out_kernel<<<2048, 256>>>(reinterpret_cast<float4*>(out), n4);
    zero_mask_kernel<<<256, 256>>>();

    // normalized subgraph scores
    score_kernel<<<1, K_SUB>>>(belong, score);

    // normalized weighted feature table (fp8 e4m3)
    prep_kernel<<<N_SEL, 128>>>(x, mw);

    // learned edges
    edge_kernel<<<E_FULL / 8, 256>>>(fe, batch, mapping, out);

    // raw edges
    raw_kernel<<<E_RAW / 256, 256>>>(re, out);
}

// round 6
// speedup vs baseline: 1.6339x; 1.1012x over previous
#include <cuda_runtime.h>
#include <math.h>

#define N_SEL   8192
#define N_FEAT  256
#define K_SUB   256
#define N_PERS  4
#define E_FULL  262144
#define E_RAW   262144
#define N_TOT   8192
#define VLEN    (N_PERS * N_FEAT)   /* 1024 */
#define EPSILON 0.5f
#define LAMB1   0.5f
#define QSCALE  254.0f
#define QINV2   (1.0f / (QSCALE * QSCALE))

// ---------------- static device scratch (allocation-free rule) --------------
__device__ signed char  g_v8[(size_t)N_SEL * VLEN];               // 8 MB int8 feature table
__device__ unsigned int g_mask[((size_t)N_SEL * N_SEL) / 32];     // 8 MB dedup bitmask
__device__ float        g_score[K_SUB];

// ---------------- score normalization (1 block, 256 threads) ----------------
__global__ void score_kernel(const int* __restrict__ belong,
                             const float* __restrict__ score) {
    __shared__ float ssum[K_SUB];
    int t = threadIdx.x;
    ssum[t] = 0.0f;
    __syncthreads();
    atomicAdd(&ssum[belong[t]], score[t]);
    __syncthreads();
    g_score[t] = score[t] / ssum[belong[t]];
}

// ---------------- build v = 0.5 * normalize(x (.) w_p) -> int8 table --------
// grid: N_SEL blocks of 128 threads; warp p handles perspective p.
// Each lane owns 8 contiguous elements -> one 8-byte store of packed int8.
__global__ void prep_kernel(const float* __restrict__ x,
                            const float* __restrict__ w) {
    int node = blockIdx.x;
    int p    = threadIdx.x >> 5;
    int lane = threadIdx.x & 31;
    const float4* xr = reinterpret_cast<const float4*>(x + (size_t)node * N_FEAT);
    const float4* wr = reinterpret_cast<const float4*>(w + (size_t)p * N_FEAT);

    float4 a0 = xr[lane * 2 + 0], a1 = xr[lane * 2 + 1];
    float4 b0 = wr[lane * 2 + 0], b1 = wr[lane * 2 + 1];
    float h[8];
    h[0] = a0.x * b0.x; h[1] = a0.y * b0.y; h[2] = a0.z * b0.z; h[3] = a0.w * b0.w;
    h[4] = a1.x * b1.x; h[5] = a1.y * b1.y; h[6] = a1.z * b1.z; h[7] = a1.w * b1.w;

    float ss = 0.0f;
#pragma unroll
    for (int k = 0; k < 8; k++) ss += h[k] * h[k];
#pragma unroll
    for (int o = 16; o > 0; o >>= 1) ss += __shfl_xor_sync(0xffffffffu, ss, o);

    // |v_elem| <= 0.5, so q = round(v * 254) fits int8 [-127, 127]
    float scale = (0.5f * QSCALE) / (sqrtf(ss) + 1e-12f);

    int q[8];
#pragma unroll
    for (int k = 0; k < 8; k++) q[k] = __float2int_rn(h[k] * scale);

    unsigned int w0 = __byte_perm((unsigned)(q[0] & 0xff) | ((unsigned)(q[1] & 0xff) << 8),
                                  (unsigned)(q[2] & 0xff) | ((unsigned)(q[3] & 0xff) << 8),
                                  0x5410);
    unsigned int w1 = __byte_perm((unsigned)(q[4] & 0xff) | ((unsigned)(q[5] & 0xff) << 8),
                                  (unsigned)(q[6] & 0xff) | ((unsigned)(q[7] & 0xff) << 8),
                                  0x5410);

    uint2* vr = reinterpret_cast<uint2*>(g_v8 + (size_t)node * VLEN + (size_t)p * N_FEAT);
    vr[lane] = make_uint2(w0, w1);
}

// ---------------- zeroing ----------------
__global__ void zero_out_kernel(float4* __restrict__ out, size_t n4) {
    size_t i = (size_t)blockIdx.x * blockDim.x + threadIdx.x;
    size_t stride = (size_t)gridDim.x * blockDim.x;
    float4 z = make_float4(0.f, 0.f, 0.f, 0.f);
    for (; i < n4; i += stride) out[i] = z;
}

__global__ void zero_mask_kernel() {
    size_t n4 = ((size_t)N_SEL * N_SEL / 32) / 4;  // uint4 count
    uint4* p = reinterpret_cast<uint4*>(g_mask);
    size_t i = (size_t)blockIdx.x * blockDim.x + threadIdx.x;
    size_t stride = (size_t)gridDim.x * blockDim.x;
    uint4 z = make_uint4(0u, 0u, 0u, 0u);
    for (; i < n4; i += stride) p[i] = z;
}

// ---------------- per-edge dot (int8 DP4A) + threshold + scatter ------------
// one warp per edge; 8 warps / block; row = 1024 int8 bytes = 64 uint4
__global__ void edge_kernel(const int* __restrict__ fe,
                            const int* __restrict__ batch,
                            const int* __restrict__ mapping,
                            float* __restrict__ out) {
    int e = blockIdx.x * 8 + (threadIdx.x >> 5);
    int lane = threadIdx.x & 31;
    if (e >= E_FULL) return;

    int i = fe[e];
    int j = fe[E_FULL + e];
    if (i == j) return;  // diagonal removed

    const uint4* vi = reinterpret_cast<const uint4*>(g_v8 + (size_t)i * VLEN);
    const uint4* vj = reinterpret_cast<const uint4*>(g_v8 + (size_t)j * VLEN);

    int acc = 0;
#pragma unroll
    for (int k = 0; k < 2; k++) {
        uint4 ua = vi[lane + k * 32];
        uint4 ub = vj[lane + k * 32];
        acc = __dp4a((int)ua.x, (int)ub.x, acc);
        acc = __dp4a((int)ua.y, (int)ub.y, acc);
        acc = __dp4a((int)ua.z, (int)ub.z, acc);
        acc = __dp4a((int)ua.w, (int)ub.w, acc);
    }
    // exact integer reduction -> deterministic
#pragma unroll
    for (int o = 16; o > 0; o >>= 1) acc += __shfl_xor_sync(0xffffffffu, acc, o);

    float sim = (float)acc * QINV2;
    if (sim > EPSILON && lane == 0) {
        // dedup: duplicate (i,j) edges contribute exactly once (mask .set semantics);
        // duplicates carry identical values, so first-writer-wins is deterministic
        size_t cell = (size_t)i * N_SEL + (size_t)j;
        unsigned bit = 1u << (cell & 31);
        unsigned old = atomicOr(&g_mask[cell >> 5], bit);
        if (!(old & bit)) {
            float wgt = g_score[batch[i]] * LAMB1;
            atomicAdd(&out[(size_t)mapping[i] * N_TOT + mapping[j]], sim * wgt);
        }
    }
}

// ---------------- raw graph edges ----------------
__global__ void raw_kernel(const int* __restrict__ re, float* __restrict__ out) {
    int e = blockIdx.x * blockDim.x + threadIdx.x;
    if (e >= E_RAW) return;
    int r0 = re[e];
    int r1 = re[E_RAW + e];
    atomicAdd(&out[(size_t)r0 * N_TOT + r1], 1.0f - LAMB1);
}

extern "C" void kernel_launch(void* const* d_in, const int* in_sizes, int n_in,
                              void* d_out, int out_size) {
    const float* x        = (const float*)d_in[0];
    const float* mw       = (const float*)d_in[1];
    const int*   batch    = (const int*)d_in[2];
    const int*   mapping  = (const int*)d_in[3];
    const int*   belong   = (const int*)d_in[4];
    const float* score    = (const float*)d_in[5];
    const int*   fe       = (const int*)d_in[6];
    const int*   re       = (const int*)d_in[7];
    float* out = (float*)d_out;

    // zero output (64M floats) and dedup mask
    size_t n4 = ((size_t)N_TOT * N_TOT) / 4;
    zero_out_kernel<<<2048, 256>>>(reinterpret_cast<float4*>(out), n4);
    zero_mask_kernel<<<256, 256>>>();

    // normalized subgraph scores
    score_kernel<<<1, K_SUB>>>(belong, score);

    // normalized weighted feature table (int8, scale 254)
    prep_kernel<<<N_SEL, 128>>>(x, mw);

    // learned edges (DP4A integer dot)
    edge_kernel<<<E_FULL / 8, 256>>>(fe, batch, mapping, out);

    // raw edges
    raw_kernel<<<E_RAW / 256, 256>>>(re, out);
}